// round 4
// baseline (speedup 1.0000x reference)
#include <cuda_runtime.h>
#include <cstdint>

#define NM 16384
__device__ float g_X[(size_t)NM*1024];
__device__ float g_G[(size_t)NM*4096];
__device__ float g_O0[(size_t)NM*1024];
__device__ unsigned g_cnt0, g_cnt1;

__device__ __forceinline__ float rna(float x){ float r; asm("cvt.rna.tf32.f32 %0,%1;":"=f"(r):"f"(x)); return r; }
__device__ __forceinline__ void cp16(void* s, const void* g){
  uint32_t d=(uint32_t)__cvta_generic_to_shared(s);
  asm volatile("cp.async.cg.shared.global [%0],[%1],16;"::"r"(d),"l"(g));
}
__device__ __forceinline__ void cpc(){ asm volatile("cp.async.commit_group;"); }
template<int N> __device__ __forceinline__ void cpw(){ asm volatile("cp.async.wait_group %0;"::"n"(N)); }
__device__ __forceinline__ unsigned ldacq(const unsigned* p){ unsigned v; asm volatile("ld.acquire.gpu.u32 %0,[%1];":"=r"(v):"l"(p)); return v; }
__device__ __forceinline__ void arrive(unsigned* p){ asm volatile("red.release.gpu.global.add.u32 [%0],1;"::"l"(p)); }
__device__ __forceinline__ void mma(float* d, const float* a, const float* b){
  asm volatile("mma.sync.aligned.m16n8k8.row.col.f32.tf32.tf32.f32 {%0,%1,%2,%3},{%4,%5,%6,%7},{%8,%9},{%0,%1,%2,%3};"
    :"+f"(d[0]),"+f"(d[1]),"+f"(d[2]),"+f"(d[3])
    :"r"(__float_as_uint(a[0])),"r"(__float_as_uint(a[1])),"r"(__float_as_uint(a[2])),"r"(__float_as_uint(a[3])),
     "r"(__float_as_uint(b[0])),"r"(__float_as_uint(b[1])));
}
__device__ __forceinline__ float sigm(float x){ return 1.f/(1.f+__expf(-x)); }

__global__ void k_init(){ g_cnt0=0u; g_cnt1=0u; }

__global__ void k_gather(const int* __restrict__ tok, const float* __restrict__ emb){
  size_t e=((size_t)blockIdx.x*256+threadIdx.x)*4;
  int row=(int)(e>>10), col=(int)(e&1023);
  *(float4*)(g_X+e)=*(const float4*)(emb+(size_t)tok[row]*1024+col);
}

__global__ void __launch_bounds__(256,2) k_gemm(const float* __restrict__ A, const float* __restrict__ W,
  const float* __restrict__ b1, const float* __restrict__ b2, float* __restrict__ C){
  __shared__ float sA[2][128*20];
  __shared__ float sB[2][64*20];
  const int tid=threadIdx.x, lane=tid&31, wid=tid>>5;
  const int wm=wid>>1, wn=wid&1, gid=lane>>2, tig=lane&3;
  const int bm=blockIdx.y, bn=blockIdx.x;
  float acc[2][4][4];
  #pragma unroll
  for(int i=0;i<2;i++)
    #pragma unroll
    for(int j=0;j<4;j++)
      #pragma unroll
      for(int k=0;k<4;k++) acc[i][j][k]=0.f;
  auto stage=[&](int ks){
    int k0=ks*16, s=ks&1;
    #pragma unroll
    for(int i=0;i<2;i++){
      int idx=i*256+tid, r=idx>>2, q=idx&3;
      cp16(&sA[s][r*20+q*4], A+(size_t)(bm*128+r)*1024+k0+q*4);
    }
    int r=tid>>2, q=tid&3;
    cp16(&sB[s][r*20+q*4], W+(size_t)(bn*64+r)*1024+k0+q*4);
  };
  stage(0); cpc();
  for(int ks=0;ks<64;ks++){
    if(ks<63){ stage(ks+1); cpc(); cpw<1>(); } else cpw<0>();
    __syncthreads();
    const float* cA=sA[ks&1]; const float* cB=sB[ks&1];
    #pragma unroll
    for(int kk=0;kk<2;kk++){
      int kb=kk*8;
      float a[2][4], b[4][2];
      #pragma unroll
      for(int mt=0;mt<2;mt++){
        int r0=wm*32+mt*16+gid;
        a[mt][0]=rna(cA[r0*20+kb+tig]);     a[mt][1]=rna(cA[(r0+8)*20+kb+tig]);
        a[mt][2]=rna(cA[r0*20+kb+tig+4]);   a[mt][3]=rna(cA[(r0+8)*20+kb+tig+4]);
      }
      #pragma unroll
      for(int nt=0;nt<4;nt++){
        int n0=wn*32+nt*8+gid;
        b[nt][0]=rna(cB[n0*20+kb+tig]); b[nt][1]=rna(cB[n0*20+kb+tig+4]);
      }
      #pragma unroll
      for(int mt=0;mt<2;mt++)
        #pragma unroll
        for(int nt=0;nt<4;nt++) mma(acc[mt][nt], a[mt], b[nt]);
    }
    __syncthreads();
  }
  #pragma unroll
  for(int nt=0;nt<4;nt++){
    int n=bn*64+wn*32+nt*8+tig*2;
    float bb0=b1[n]+b2[n], bb1=b1[n+1]+b2[n+1];
    #pragma unroll
    for(int mt=0;mt<2;mt++){
      size_t m0=bm*128+wm*32+mt*16+gid;
      float2 v0=make_float2(acc[mt][nt][0]+bb0, acc[mt][nt][1]+bb1);
      float2 v1=make_float2(acc[mt][nt][2]+bb0, acc[mt][nt][3]+bb1);
      *(float2*)(C+m0*4096+n)=v0;
      *(float2*)(C+(m0+8)*4096+n)=v1;
    }
  }
}

// persistent recurrence: 128 CTAs, CTA owns units [8*bid,8*bid+8) x 4 gates
__global__ void __launch_bounds__(256,1) k_rec(const float* __restrict__ Whh,
  const float* __restrict__ h0, const float* __restrict__ c0,
  const float* __restrict__ G, float* __restrict__ hist,
  float* __restrict__ hF, float* __restrict__ cF, unsigned* cnt){
  extern __shared__ float sm[];
  float* Ws=sm;              // 32 x 1028
  float* Hs=sm+32896;        // 2 x (32 x 260)
  float* Gs=sm+49536;        // 32 x 33
  float* Red=Hs;             // alias buf0 after compute (8x32x32)
  const int tid=threadIdx.x, lane=tid&31, w=tid>>5;
  const int gid=lane>>2, tig=lane&3, u0=blockIdx.x*8;
  const int cb=tid>>3, cu=tid&7;

  #pragma unroll 4
  for(int i=0;i<32;i++){
    int idx=i*256+tid, r=idx>>8, q=idx&255;
    cp16(Ws+r*1028+q*4, Whh+(size_t)((r>>3)*1024+u0+(r&7))*1024+q*4);
  }
  cpc(); cpw<0>(); __syncthreads();
  for(int i=tid;i<32*1028;i+=256) Ws[i]=rna(Ws[i]);
  float creg=c0[cb*1024+u0+cu];
  __syncthreads();

  float acc[2][4][4];
  auto stage=[&](const float* hp, int c){
    float* dst=Hs+(c&1)*8320;
    #pragma unroll
    for(int i=0;i<8;i++){
      int idx=i*256+tid, r=idx>>6, q=idx&63;
      cp16(dst+r*260+q*4, hp+(size_t)r*1024+c*256+q*4);
    }
  };
  auto comp=[&](int c){
    const float* Hc=Hs+(c&1)*8320;
    const int kw=w*32;
    #pragma unroll
    for(int kk=0;kk<4;kk++){
      int kb=kw+kk*8, gk=c*256+kb;
      float a[2][4], b[4][2];
      #pragma unroll
      for(int mt=0;mt<2;mt++){
        int r0=mt*16+gid;
        a[mt][0]=rna(Hc[r0*260+kb+tig]);   a[mt][1]=rna(Hc[(r0+8)*260+kb+tig]);
        a[mt][2]=rna(Hc[r0*260+kb+tig+4]); a[mt][3]=rna(Hc[(r0+8)*260+kb+tig+4]);
      }
      #pragma unroll
      for(int nt=0;nt<4;nt++){
        int n0=nt*8+gid;
        b[nt][0]=Ws[n0*1028+gk+tig]; b[nt][1]=Ws[n0*1028+gk+tig+4];
      }
      #pragma unroll
      for(int mt=0;mt<2;mt++)
        #pragma unroll
        for(int nt=0;nt<4;nt++) mma(acc[mt][nt], a[mt], b[nt]);
    }
  };

  for(int t=0;t<512;t++){
    if(t){
      if(tid==0){ while(ldacq(cnt)<128u*(unsigned)t) __nanosleep(64); }
      __syncthreads();
    }
    const float* hp = t ? hist+(size_t)(t-1)*32768 : h0;
    const float* gp = G+(size_t)(t*32+cb)*4096+u0+cu;
    float gpi=gp[0], gpf=gp[1024], gpg=gp[2048], gpo=gp[3072];
    stage(hp,0); cpc(); stage(hp,1); cpc();
    #pragma unroll
    for(int i=0;i<2;i++)
      #pragma unroll
      for(int j=0;j<4;j++)
        #pragma unroll
        for(int k=0;k<4;k++) acc[i][j][k]=0.f;
    cpw<1>(); __syncthreads(); comp(0); __syncthreads(); stage(hp,2); cpc();
    cpw<1>(); __syncthreads(); comp(1); __syncthreads(); stage(hp,3); cpc();
    cpw<1>(); __syncthreads(); comp(2); __syncthreads();
    cpw<0>(); __syncthreads(); comp(3); __syncthreads();
    #pragma unroll
    for(int mt=0;mt<2;mt++)
      #pragma unroll
      for(int nt=0;nt<4;nt++){
        int m=mt*16+gid, n=nt*8+tig*2;
        Red[w*1024+m*32+n]  =acc[mt][nt][0]; Red[w*1024+m*32+n+1]    =acc[mt][nt][1];
        Red[w*1024+(m+8)*32+n]=acc[mt][nt][2]; Red[w*1024+(m+8)*32+n+1]=acc[mt][nt][3];
      }
    __syncthreads();
    {
      const float4* R4=(const float4*)Red;
      float4 s=make_float4(0.f,0.f,0.f,0.f);
      #pragma unroll
      for(int ww=0;ww<8;ww++){ float4 v=R4[ww*256+tid]; s.x+=v.x; s.y+=v.y; s.z+=v.z; s.w+=v.w; }
      float* gdst=Gs+(tid>>3)*33+(tid&7)*4;
      gdst[0]=s.x; gdst[1]=s.y; gdst[2]=s.z; gdst[3]=s.w;
    }
    __syncthreads();
    float iv=sigm(Gs[cb*33+cu]+gpi);
    float fv=sigm(Gs[cb*33+cu+8]+gpf);
    float gv=tanhf(Gs[cb*33+cu+16]+gpg);
    float ov=sigm(Gs[cb*33+cu+24]+gpo);
    creg=fv*creg+iv*gv;
    float hv=ov*tanhf(creg);
    hist[(size_t)t*32768+cb*1024+u0+cu]=hv;
    if(t==511){ hF[cb*1024+u0+cu]=hv; cF[cb*1024+u0+cu]=creg; }
    __syncthreads();
    if(tid==0) arrive(cnt);
  }
}

extern "C" void kernel_launch(void* const* d_in, const int* in_sizes, int n_in,
                              void* d_out, int out_size){
  const int*   tok=(const int*)d_in[0];
  const float* h0 =(const float*)d_in[1];
  const float* c0 =(const float*)d_in[2];
  const float* emb=(const float*)d_in[3];
  const float* Wi0=(const float*)d_in[4];
  const float* Wh0=(const float*)d_in[5];
  const float* bi0=(const float*)d_in[6];
  const float* bh0=(const float*)d_in[7];
  const float* Wi1=(const float*)d_in[8];
  const float* Wh1=(const float*)d_in[9];
  const float* bi1=(const float*)d_in[10];
  const float* bh1=(const float*)d_in[11];
  float* out=(float*)d_out;

  float *pX,*pG,*pO0; unsigned *pc0,*pc1;
  cudaGetSymbolAddress((void**)&pX,  g_X);
  cudaGetSymbolAddress((void**)&pG,  g_G);
  cudaGetSymbolAddress((void**)&pO0, g_O0);
  cudaGetSymbolAddress((void**)&pc0, g_cnt0);
  cudaGetSymbolAddress((void**)&pc1, g_cnt1);
  cudaFuncSetAttribute(k_rec, cudaFuncAttributeMaxDynamicSharedMemorySize, 202368);

  float* hFb=out+16777216;   // outputs 512*32*1024
  float* cFb=out+16842752;   // + hF 2*32*1024

  k_init<<<1,32>>>();
  k_gather<<<16384,256>>>(tok, emb);
  k_gemm<<<dim3(64,128),256>>>(pX, Wi0, bi0, bh0, pG);
  k_rec<<<128,256,202368>>>(Wh0, h0, c0, pG, pO0, hFb, cFb, pc0);
  k_gemm<<<dim3(64,128),256>>>(pO0, Wi1, bi1, bh1, pG);
  k_rec<<<128,256,202368>>>(Wh1, h0+32768, c0+32768, pG, out, hFb+32768, cFb+32768, pc1);
}

// round 6
// speedup vs baseline: 1.6018x; 1.6018x over previous
#include <cuda_runtime.h>
#include <cuda.h>
#include <cstdint>

#define NM 16384
__device__ float g_X  [(size_t)NM*1024];
__device__ float g_G  [(size_t)NM*4096];
__device__ float g_H0 [(size_t)16416*1024];
__device__ float g_H1 [(size_t)16416*1024];
__device__ float g_W0c[(size_t)4096*1024];
__device__ float g_W1c[(size_t)4096*1024];
__device__ unsigned g_cnt0, g_cnt1;

__device__ __forceinline__ float rna(float x){ float r; asm("cvt.rna.tf32.f32 %0,%1;":"=f"(r):"f"(x)); return r; }
__device__ __forceinline__ uint32_t s32(const void* p){ return (uint32_t)__cvta_generic_to_shared(p); }
__device__ __forceinline__ void cp16(void* s, const void* g){
  asm volatile("cp.async.cg.shared.global [%0],[%1],16;"::"r"(s32(s)),"l"(g));
}
__device__ __forceinline__ void cpc(){ asm volatile("cp.async.commit_group;"); }
template<int N> __device__ __forceinline__ void cpw(){ asm volatile("cp.async.wait_group %0;"::"n"(N)); }
__device__ __forceinline__ unsigned ldacq(const unsigned* p){ unsigned v; asm volatile("ld.acquire.gpu.u32 %0,[%1];":"=r"(v):"l"(p)); return v; }
__device__ __forceinline__ void arrive(unsigned* p){ asm volatile("red.release.gpu.global.add.u32 [%0],1;"::"l"(p)); }
__device__ __forceinline__ void mbar_init(uint64_t* m, unsigned c){
  asm volatile("mbarrier.init.shared.b64 [%0],%1;"::"r"(s32(m)),"r"(c):"memory");
}
__device__ __forceinline__ void mexpect(uint64_t* m, unsigned bytes){
  asm volatile("mbarrier.arrive.expect_tx.shared.b64 _,[%0],%1;"::"r"(s32(m)),"r"(bytes):"memory");
}
__device__ __forceinline__ void mwait(uint64_t* m, int ph){
  uint32_t a=s32(m);
  asm volatile("{\n\t.reg .pred P;\nLW%=:\n\tmbarrier.try_wait.parity.shared::cta.b64 P,[%0],%1,0x989680;\n\t@P bra LD%=;\n\tbra LW%=;\nLD%=:\n\t}"::"r"(a),"r"(ph):"memory");
}
__device__ __forceinline__ void tma2d(uint32_t smem, const void* map, int x, int y, uint64_t* mb){
  asm volatile("cp.async.bulk.tensor.2d.shared::cta.global.tile.mbarrier::complete_tx::bytes [%0],[%1,{%2,%3}],[%4];"
    ::"r"(smem),"l"(map),"r"(x),"r"(y),"r"(s32(mb)):"memory");
}
__device__ __forceinline__ void fpa(){ asm volatile("fence.proxy.async;"); }
__device__ __forceinline__ void mma(float* d, const float* a, const float* b){
  asm volatile("mma.sync.aligned.m16n8k8.row.col.f32.tf32.tf32.f32 {%0,%1,%2,%3},{%4,%5,%6,%7},{%8,%9},{%0,%1,%2,%3};"
    :"+f"(d[0]),"+f"(d[1]),"+f"(d[2]),"+f"(d[3])
    :"r"(__float_as_uint(a[0])),"r"(__float_as_uint(a[1])),"r"(__float_as_uint(a[2])),"r"(__float_as_uint(a[3])),
     "r"(__float_as_uint(b[0])),"r"(__float_as_uint(b[1])));
}
__device__ __forceinline__ float sigm(float x){ return 1.f/(1.f+__expf(-x)); }

__global__ void k_init(const float* __restrict__ h0){
  int i=blockIdx.x*256+threadIdx.x;
  if(i==0){ g_cnt0=0u; g_cnt1=0u; }
  float v=h0[i];
  if(i<32768) g_H0[i]=v; else g_H1[i-32768]=v;
}

__global__ void k_gather(const int* __restrict__ tok, const float* __restrict__ emb){
  size_t e=((size_t)blockIdx.x*256+threadIdx.x)*4;
  int row=(int)(e>>10), col=(int)(e&1023);
  float4 v=*(const float4*)(emb+(size_t)tok[row]*1024+col);
  v.x=rna(v.x); v.y=rna(v.y); v.z=rna(v.z); v.w=rna(v.w);
  *(float4*)(g_X+e)=v;
}

__global__ void k_prepw(const float* __restrict__ w0, const float* __restrict__ w1){
  size_t e=((size_t)blockIdx.x*256+threadIdx.x)*4;
  float4 a=*(const float4*)(w0+e);
  a.x=rna(a.x); a.y=rna(a.y); a.z=rna(a.z); a.w=rna(a.w);
  *(float4*)(g_W0c+e)=a;
  float4 b=*(const float4*)(w1+e);
  b.x=rna(b.x); b.y=rna(b.y); b.z=rna(b.z); b.w=rna(b.w);
  *(float4*)(g_W1c+e)=b;
}

__global__ void k_copy(float4* __restrict__ out){
  size_t i=(size_t)blockIdx.x*256+threadIdx.x;
  out[i]=((const float4*)(g_H1+32768))[i];
}

// ---------------- GEMM: C[16384,4096] = A[16384,1024] @ W[4096,1024]^T + b ----
template<bool RNA_A>
__global__ void __launch_bounds__(256,2) k_gemm(
  const __grid_constant__ CUtensorMap mA, const __grid_constant__ CUtensorMap mW,
  int yoff, const float* __restrict__ b1, const float* __restrict__ b2,
  float* __restrict__ C){
  extern __shared__ float smraw[];
  float* base=(float*)((((uintptr_t)smraw)+1023)&~(uintptr_t)1023);
  float* sA=base; float* sB=base+12288;
  uint64_t* mb=(uint64_t*)(base+24576);
  const int tid=threadIdx.x, lane=tid&31, wid=tid>>5;
  const int wm=wid>>1, wn=wid&1, gid=lane>>2, tig=lane&3;
  const int bm=blockIdx.y, bn=blockIdx.x;
  const void* pA=(const void*)&mA; const void* pW=(const void*)&mW;
  uint32_t sa0=s32(sA), sb0=s32(sB);
  if(tid==0){ mbar_init(mb+0,1); mbar_init(mb+1,1); mbar_init(mb+2,1); fpa(); }
  __syncthreads();
  auto issue=[&](int ks){
    if(tid==0){
      int s=ks%3;
      mexpect(mb+s,32768);
      tma2d(sa0+s*16384, pA, ks*32, bm*128+yoff, mb+s);
      tma2d(sb0+s*16384, pW, ks*32, bn*128,      mb+s);
    }
  };
  issue(0); issue(1); issue(2);
  float acc[2][8][4];
  #pragma unroll
  for(int i=0;i<2;i++)
    #pragma unroll
    for(int j=0;j<8;j++)
      #pragma unroll
      for(int k=0;k<4;k++) acc[i][j][k]=0.f;
  for(int ks=0;ks<32;ks++){
    int s=ks%3;
    mwait(mb+s,(ks/3)&1);
    const float* cA=sA+s*4096; const float* cB=sB+s*4096;
    #pragma unroll
    for(int kk=0;kk<4;kk++){
      int sx0=(((kk*2)^gid)<<2)+tig, sx1=(((kk*2+1)^gid)<<2)+tig;
      float a[2][4], b[8][2];
      #pragma unroll
      for(int mt=0;mt<2;mt++){
        int r0=wm*32+mt*16+gid;
        float v0=cA[r0*32+sx0], v1=cA[(r0+8)*32+sx0];
        float v2=cA[r0*32+sx1], v3=cA[(r0+8)*32+sx1];
        if(RNA_A){ v0=rna(v0); v1=rna(v1); v2=rna(v2); v3=rna(v3); }
        a[mt][0]=v0; a[mt][1]=v1; a[mt][2]=v2; a[mt][3]=v3;
      }
      #pragma unroll
      for(int nt=0;nt<8;nt++){
        int n0=wn*64+nt*8+gid;
        b[nt][0]=cB[n0*32+sx0]; b[nt][1]=cB[n0*32+sx1];
      }
      #pragma unroll
      for(int mt=0;mt<2;mt++)
        #pragma unroll
        for(int nt=0;nt<8;nt++) mma(acc[mt][nt], a[mt], b[nt]);
    }
    __syncthreads();
    if(ks+3<32) issue(ks+3);
  }
  #pragma unroll
  for(int nt=0;nt<8;nt++){
    int n=bn*128+wn*64+nt*8+tig*2;
    float bb0=b1[n]+b2[n], bb1=b1[n+1]+b2[n+1];
    #pragma unroll
    for(int mt=0;mt<2;mt++){
      size_t m0=(size_t)bm*128+wm*32+mt*16+gid;
      *(float2*)(C+m0*4096+n)    =make_float2(acc[mt][nt][0]+bb0, acc[mt][nt][1]+bb1);
      *(float2*)(C+(m0+8)*4096+n)=make_float2(acc[mt][nt][2]+bb0, acc[mt][nt][3]+bb1);
    }
  }
}

// ---------------- persistent recurrence ------------------------------------
__global__ void __launch_bounds__(256,1) k_rec(
  const __grid_constant__ CUtensorMap mH,
  const float* __restrict__ Whh, const float* __restrict__ c0l,
  const float* __restrict__ G, float* __restrict__ hist,
  float* __restrict__ hFl, float* __restrict__ cFl, unsigned* cnt){
  extern __shared__ float smraw[];
  float* base=(float*)((((uintptr_t)smraw)+1023)&~(uintptr_t)1023);
  float* Hs=base;               // 2 x 8192 floats (64KB, 1024-aligned)
  float* Ws=base+16384;         // 32 x 1028
  float* Gs=base+49280;         // 32 x 33
  uint64_t* mb=(uint64_t*)(base+50336);
  float* Red=Hs;
  const int tid=threadIdx.x, lane=tid&31, w=tid>>5;
  const int gid=lane>>2, tig=lane&3, u0=blockIdx.x*8;
  const int cb=tid>>3, cu=tid&7;
  const void* pH=(const void*)&mH;
  uint32_t hs0=s32(Hs);

  if(tid==0){ mbar_init(mb+0,1); mbar_init(mb+1,1); fpa(); }
  #pragma unroll 4
  for(int i=0;i<32;i++){
    int idx=i*256+tid, r=idx>>8, q=idx&255;
    cp16(Ws+r*1028+q*4, Whh+(size_t)((r>>3)*1024+u0+(r&7))*1024+q*4);
  }
  cpc(); cpw<0>(); __syncthreads();
  for(int i=tid;i<32896;i+=256) Ws[i]=rna(Ws[i]);
  float creg=c0l[cb*1024+u0+cu];
  __syncthreads();

  float acc[2][4][4];
  auto comp=[&](int c){
    const float* Hc=Hs+(c&1)*8192;
    const int kb0=w*1024;
    #pragma unroll
    for(int kk=0;kk<4;kk++){
      int sx0=(((kk*2)^gid)<<2)+tig, sx1=(((kk*2+1)^gid)<<2)+tig;
      float a[2][4], b[4][2];
      #pragma unroll
      for(int mt=0;mt<2;mt++){
        int r0=mt*16+gid;
        a[mt][0]=rna(Hc[kb0+r0*32+sx0]);
        a[mt][1]=rna(Hc[kb0+(r0+8)*32+sx0]);
        a[mt][2]=rna(Hc[kb0+r0*32+sx1]);
        a[mt][3]=rna(Hc[kb0+(r0+8)*32+sx1]);
      }
      int gk=c*256+w*32+kk*8;
      #pragma unroll
      for(int nt=0;nt<4;nt++){
        int n0=nt*8+gid;
        b[nt][0]=Ws[n0*1028+gk+tig]; b[nt][1]=Ws[n0*1028+gk+tig+4];
      }
      #pragma unroll
      for(int mt=0;mt<2;mt++)
        #pragma unroll
        for(int nt=0;nt<4;nt++) mma(acc[mt][nt], a[mt], b[nt]);
    }
  };

  for(int t=0;t<512;t++){
    if(t && tid==0){
      while(ldacq(cnt)<128u*(unsigned)t) __nanosleep(32);
      fpa();
    }
    __syncthreads();
    const float* gp=G+(size_t)(t*32+cb)*4096+u0+cu;
    float gpi=gp[0], gpf=gp[1024], gpg=gp[2048], gpo=gp[3072];
    if(tid==0){
      mexpect(mb+0,32768);
      #pragma unroll
      for(int s=0;s<8;s++) tma2d(hs0+s*4096, pH, s*32, t*32, mb+0);
      mexpect(mb+1,32768);
      #pragma unroll
      for(int s=0;s<8;s++) tma2d(hs0+32768+s*4096, pH, 256+s*32, t*32, mb+1);
    }
    #pragma unroll
    for(int i=0;i<2;i++)
      #pragma unroll
      for(int j=0;j<4;j++)
        #pragma unroll
        for(int k=0;k<4;k++) acc[i][j][k]=0.f;
    mwait(mb+0,0); comp(0); __syncthreads();
    if(tid==0){
      mexpect(mb+0,32768);
      #pragma unroll
      for(int s=0;s<8;s++) tma2d(hs0+s*4096, pH, 512+s*32, t*32, mb+0);
    }
    mwait(mb+1,0); comp(1); __syncthreads();
    if(tid==0){
      mexpect(mb+1,32768);
      #pragma unroll
      for(int s=0;s<8;s++) tma2d(hs0+32768+s*4096, pH, 768+s*32, t*32, mb+1);
    }
    mwait(mb+0,1); comp(2); __syncthreads();
    mwait(mb+1,1); comp(3); __syncthreads();

    #pragma unroll
    for(int mt=0;mt<2;mt++)
      #pragma unroll
      for(int nt=0;nt<4;nt++){
        int m=mt*16+gid, n=nt*8+tig*2;
        Red[w*1024+m*32+n]    =acc[mt][nt][0]; Red[w*1024+m*32+n+1]    =acc[mt][nt][1];
        Red[w*1024+(m+8)*32+n]=acc[mt][nt][2]; Red[w*1024+(m+8)*32+n+1]=acc[mt][nt][3];
      }
    __syncthreads();
    {
      const float4* R4=(const float4*)Red;
      float4 s4=make_float4(0.f,0.f,0.f,0.f);
      #pragma unroll
      for(int ww=0;ww<8;ww++){ float4 v=R4[ww*256+tid]; s4.x+=v.x; s4.y+=v.y; s4.z+=v.z; s4.w+=v.w; }
      float* gdst=Gs+(tid>>3)*33+(tid&7)*4;
      gdst[0]=s4.x; gdst[1]=s4.y; gdst[2]=s4.z; gdst[3]=s4.w;
    }
    __syncthreads();
    float iv=sigm(Gs[cb*33+cu]+gpi);
    float fv=sigm(Gs[cb*33+cu+8]+gpf);
    float gv=tanhf(Gs[cb*33+cu+16]+gpg);
    float ov=sigm(Gs[cb*33+cu+24]+gpo);
    creg=fv*creg+iv*gv;
    float hv=ov*tanhf(creg);
    hist[(size_t)(t+1)*32768+cb*1024+u0+cu]=hv;
    if(t==511){ hFl[cb*1024+u0+cu]=hv; cFl[cb*1024+u0+cu]=creg; }
    __syncthreads();
    if(tid==0) arrive(cnt);
  }
}

// ---------------- host ------------------------------------------------------
typedef CUresult (*EncodeFn)(CUtensorMap*, CUtensorMapDataType, cuuint32_t, void*,
                             const cuuint64_t*, const cuuint64_t*, const cuuint32_t*,
                             const cuuint32_t*, CUtensorMapInterleave, CUtensorMapSwizzle,
                             CUtensorMapL2promotion, CUtensorMapFloatOOBfill);

static EncodeFn get_encode(){
  static EncodeFn fn = nullptr;
  if(!fn){
    void* p = nullptr;
#if CUDART_VERSION >= 12050
    cudaDriverEntryPointQueryResult qr;
    cudaGetDriverEntryPointByVersion("cuTensorMapEncodeTiled", &p, 12000,
                                     cudaEnableDefault, &qr);
    if(!p) cudaGetDriverEntryPoint("cuTensorMapEncodeTiled", &p, cudaEnableDefault, &qr);
#else
    cudaGetDriverEntryPoint("cuTensorMapEncodeTiled", &p, cudaEnableDefault);
#endif
    fn = (EncodeFn)p;
  }
  return fn;
}

static void mk2d(CUtensorMap* m, void* p, uint64_t h, uint32_t bh){
  cuuint64_t dims[2]={1024,h};
  cuuint64_t st[1]={4096};
  cuuint32_t box[2]={32,bh};
  cuuint32_t es[2]={1,1};
  get_encode()(m, CU_TENSOR_MAP_DATA_TYPE_FLOAT32, 2, p, dims, st, box, es,
    CU_TENSOR_MAP_INTERLEAVE_NONE, CU_TENSOR_MAP_SWIZZLE_128B,
    CU_TENSOR_MAP_L2_PROMOTION_L2_128B, CU_TENSOR_MAP_FLOAT_OOB_FILL_NONE);
}

extern "C" void kernel_launch(void* const* d_in, const int* in_sizes, int n_in,
                              void* d_out, int out_size){
  const int*   tok=(const int*)d_in[0];
  const float* h0 =(const float*)d_in[1];
  const float* c0 =(const float*)d_in[2];
  const float* emb=(const float*)d_in[3];
  const float* Wi0=(const float*)d_in[4];
  const float* Wh0=(const float*)d_in[5];
  const float* bi0=(const float*)d_in[6];
  const float* bh0=(const float*)d_in[7];
  const float* Wi1=(const float*)d_in[8];
  const float* Wh1=(const float*)d_in[9];
  const float* bi1=(const float*)d_in[10];
  const float* bh1=(const float*)d_in[11];
  float* out=(float*)d_out;

  float *pX,*pG,*pH0,*pH1,*pW0,*pW1; unsigned *pc0,*pc1;
  cudaGetSymbolAddress((void**)&pX,  g_X);
  cudaGetSymbolAddress((void**)&pG,  g_G);
  cudaGetSymbolAddress((void**)&pH0, g_H0);
  cudaGetSymbolAddress((void**)&pH1, g_H1);
  cudaGetSymbolAddress((void**)&pW0, g_W0c);
  cudaGetSymbolAddress((void**)&pW1, g_W1c);
  cudaGetSymbolAddress((void**)&pc0, g_cnt0);
  cudaGetSymbolAddress((void**)&pc1, g_cnt1);

  CUtensorMap mX, mW0m, mW1m, mA1, mH0r, mH1r;
  mk2d(&mX,  pX, 16384,128);
  mk2d(&mW0m,pW0, 4096,128);
  mk2d(&mW1m,pW1, 4096,128);
  mk2d(&mA1, pH0,16416,128);
  mk2d(&mH0r,pH0,16416, 32);
  mk2d(&mH1r,pH1,16416, 32);

  cudaFuncSetAttribute(k_gemm<false>, cudaFuncAttributeMaxDynamicSharedMemorySize, 99352);
  cudaFuncSetAttribute(k_gemm<true>,  cudaFuncAttributeMaxDynamicSharedMemorySize, 99352);
  cudaFuncSetAttribute(k_rec,         cudaFuncAttributeMaxDynamicSharedMemorySize, 202384);

  float* hFb=out+16777216;
  float* cFb=out+16842752;

  k_init  <<<256,256>>>(h0);
  k_gather<<<16384,256>>>(tok, emb);
  k_prepw <<<4096,256>>>(Wi0, Wi1);
  k_gemm<false><<<dim3(32,128),256, 99352>>>(mX,  mW0m, 0,  bi0, bh0, pG);
  k_rec        <<<128,256,202384>>>(mH0r, Wh0, c0,       pG, pH0, hFb,       cFb,       pc0);
  k_gemm<true> <<<dim3(32,128),256, 99352>>>(mA1, mW1m, 32, bi1, bh1, pG);
  k_rec        <<<128,256,202384>>>(mH1r, Wh1, c0+32768, pG, pH1, hFb+32768, cFb+32768, pc1);
  k_copy  <<<16384,256>>>((float4*)out);
}